// round 9
// baseline (speedup 1.0000x reference)
#include <cuda_runtime.h>
#include <cuda_bf16.h>

// Yolov1 loss — persistent single-wave kernel, 3-stage cp.async ring per warp.
// B=16384, cells = 802816 = 25088 tiles of 32 cells.
// 296 blocks (148 SM * 2) * 8 warps = 2368 warp-streams; stream s handles tiles
// s, s+2368, ... (10 or 11 tiles; uniform within each block).
// Cell layout: [0:2) conf, [2:10) boxes (NB,4), [10:30) class logits.

#define NBLOCKS  296
#define NTHREADS 256
#define NSTREAMS (NBLOCKS * 8)   // 2368
#define NTILES   25088
#define NSTAGES  3

__device__ float g_partials[NBLOCKS];
__device__ unsigned int g_done = 0;   // atomicInc mod NBLOCKS -> self-resetting

__device__ __forceinline__ float fsig(float x) {
    float t;
    asm("tanh.approx.f32 %0, %1;" : "=f"(t) : "f"(x * 0.5f));
    return fmaf(t, 0.5f, 0.5f);
}
__device__ __forceinline__ float fsqrt_a(float x) {
    float r;
    asm("sqrt.approx.f32 %0, %1;" : "=f"(r) : "f"(x));
    return r;
}
__device__ __forceinline__ unsigned int smem_u32(const void* p) {
    return (unsigned int)__cvta_generic_to_shared(p);
}

// One cell's loss. p = 30 floats in smem; target data already in registers.
__device__ __forceinline__ float cell_loss(const float* __restrict__ p, int t,
                                           float4 tb, int g, int tc)
{
    const int s = t % 49;
    const float xg = (float)(s % 7);
    const float yg = (float)(s / 7);
    const float inv7 = 1.0f / 7.0f;
    const float tox = tb.x, toy = tb.y, tw = tb.z, th = tb.w;

    const float conf0 = fsig(p[0]);
    const float conf1 = fsig(p[1]);
    float pb[2][4];
    #pragma unroll
    for (int nb = 0; nb < 2; nb++)
        #pragma unroll
        for (int k = 0; k < 4; k++)
            pb[nb][k] = fsig(p[2 + nb * 4 + k]);

    float esum = 0.0f, et = 0.0f;
    #pragma unroll
    for (int j = 0; j < 20; j++) {
        const float e = __expf(p[10 + j]);
        esum += e;
        if (j == tc) et = e;
    }
    const float cls_t = __fdividef(et, esum);

    const float tcx = (xg + tox) * inv7;
    const float tcy = (yg + toy) * inv7;
    float iou[2];
    #pragma unroll
    for (int nb = 0; nb < 2; nb++) {
        const float pcx = (xg + pb[nb][0]) * inv7;
        const float pcy = (yg + pb[nb][1]) * inv7;
        const float pw = pb[nb][2], ph = pb[nb][3];
        const float tb_ = fminf(tcx + tw * 0.5f, pcx + pw * 0.5f)
                        - fmaxf(tcx - tw * 0.5f, pcx - pw * 0.5f);
        const float lr_ = fminf(tcy + th * 0.5f, pcy + ph * 0.5f)
                        - fmaxf(tcy - th * 0.5f, pcy - ph * 0.5f);
        const float inter = (tb_ < 0.0f || lr_ < 0.0f) ? 0.0f : tb_ * lr_;
        iou[nb] = __fdividef(inter, tw * th + pw * ph - inter);
    }

    const int best = (iou[1] > iou[0]) ? 1 : 0;
    const float iou_b  = iou[best];
    const float conf_b = best ? conf1 : conf0;

    const float d0 = pb[best][0] - tox;
    const float d1 = pb[best][1] - toy;
    const float d2 = fsqrt_a(pb[best][2]) - fsqrt_a(tw);
    const float d3 = fsqrt_a(pb[best][3]) - fsqrt_a(th);
    const float coord = d0 * d0 + d1 * d1 + d2 * d2 + d3 * d3;

    const float dc = conf_b - iou_b;
    const float dl = 1.0f - cls_t;
    const float obj_loss   = 5.0f * coord + dc * dc + dl * dl;
    const float noobj_loss = 0.5f * (conf0 * conf0 + conf1 * conf1);
    return (g == 1) ? obj_loss : noobj_loss;
}

// Issue one tile's cp.async copies (240 float4 spread over the warp), no commit.
__device__ __forceinline__ void issue_tile(float* __restrict__ dst,
                                           const float4* __restrict__ pred4,
                                           int tile, int lane)
{
    const float4* src = pred4 + (long)tile * 240;
    #pragma unroll
    for (int i = 0; i < 8; i++) {
        const int idx = lane + i * 32;
        if (idx < 240) {
            const unsigned int da = smem_u32(dst + idx * 4);
            asm volatile("cp.async.cg.shared.global [%0], [%1], 16;"
                         :: "r"(da), "l"(src + idx));
        }
    }
}

__global__ __launch_bounds__(NTHREADS, 2)
void yolo_loss_kernel(const float* __restrict__ pred,
                      const int*   __restrict__ grid,
                      const float* __restrict__ tbox,
                      const int*   __restrict__ tcls,
                      float* __restrict__ out)
{
    // 3 stages * 8 warps * (32 cells * 30 words) = 23040 words = 92160 B
    __shared__ float sp[NSTAGES * 8 * 960];

    const int lane = threadIdx.x & 31;
    const int wid  = threadIdx.x >> 5;
    const int stream = blockIdx.x * 8 + wid;

    float* stg[NSTAGES];
    #pragma unroll
    for (int i = 0; i < NSTAGES; i++) stg[i] = sp + (i * 8 + wid) * 960;

    const float4* const tbox4 = reinterpret_cast<const float4*>(tbox);
    const float4* const pred4 = reinterpret_cast<const float4*>(pred);

    // ---- prologue: fill stages 0 and 1 ----
    issue_tile(stg[0], pred4, stream, lane);
    asm volatile("cp.async.commit_group;");
    {
        const int t1 = stream + NSTREAMS;
        if (t1 < NTILES) issue_tile(stg[1], pred4, t1, lane);
        asm volatile("cp.async.commit_group;");
    }
    int c0 = stream * 32 + lane;
    float4 tb = __ldg(tbox4 + c0);
    int    g  = __ldg(grid + c0);
    int    tc = __ldg(tcls + c0);

    float v = 0.0f;

    for (int it = 0; ; it++) {
        // issue tile it+2 into stage (it+2)%3; commit always (uniform group count)
        const int t2 = stream + (it + 2) * NSTREAMS;
        if (t2 < NTILES) issue_tile(stg[(it + 2) % NSTAGES], pred4, t2, lane);
        asm volatile("cp.async.commit_group;");

        // register-prefetch targets of tile it+1 (overlaps current compute)
        const int t1 = stream + (it + 1) * NSTREAMS;
        const bool valid1 = (t1 < NTILES);
        float4 tbn; int gn = 0, tcn = 0;
        if (valid1) {
            const int cn = t1 * 32 + lane;
            tbn = __ldg(tbox4 + cn);
            gn  = __ldg(grid + cn);
            tcn = __ldg(tcls + cn);
        }

        // two newest groups (it+1, it+2) may remain pending -> tile it is done
        asm volatile("cp.async.wait_group 2;");
        __syncwarp();

        const float* p = stg[it % NSTAGES] + lane * 30;
        const int t_cell = (stream + it * NSTREAMS) * 32 + lane;
        v += cell_loss(p, t_cell, tb, g, tc);

        if (!valid1) break;
        tb = tbn; g = gn; tc = tcn;
    }

    // ---- block reduction -> g_partials[blockIdx.x] ----
    #pragma unroll
    for (int o = 16; o; o >>= 1) v += __shfl_down_sync(0xffffffffu, v, o);
    __shared__ float wsum[NTHREADS / 32];
    __shared__ bool s_last;
    if (lane == 0) wsum[wid] = v;
    __syncthreads();
    if (threadIdx.x < NTHREADS / 32) {
        v = wsum[threadIdx.x];
        #pragma unroll
        for (int o = NTHREADS / 64; o; o >>= 1) v += __shfl_down_sync(0xffu, v, o);
        if (threadIdx.x == 0) {
            g_partials[blockIdx.x] = v;
            __threadfence();
            unsigned int prev = atomicInc(&g_done, NBLOCKS - 1);
            s_last = (prev == NBLOCKS - 1);
        }
    }
    __syncthreads();

    // ---- last-arriving block: deterministic final reduction ----
    if (s_last) {
        double acc = 0.0;
        for (int i = threadIdx.x; i < NBLOCKS; i += NTHREADS)
            acc += (double)g_partials[i];
        #pragma unroll
        for (int o = 16; o; o >>= 1) acc += __shfl_down_sync(0xffffffffu, acc, o);
        __shared__ double ws[NTHREADS / 32];
        if (lane == 0) ws[wid] = acc;
        __syncthreads();
        if (threadIdx.x == 0) {
            double sum = 0.0;
            #pragma unroll
            for (int i = 0; i < NTHREADS / 32; i++) sum += ws[i];
            out[0] = (float)(sum / 16384.0);
        }
    }
}

extern "C" void kernel_launch(void* const* d_in, const int* in_sizes, int n_in,
                              void* d_out, int out_size)
{
    const float* pred = (const float*)d_in[0];   // (B, 1470) f32
    const int*   grid = (const int*)  d_in[1];   // (B, 7, 7) i32
    const float* tbox = (const float*)d_in[2];   // (B, 7, 7, 4) f32
    const int*   tcls = (const int*)  d_in[3];   // (B, 7, 7) i32
    float* out = (float*)d_out;

    yolo_loss_kernel<<<NBLOCKS, NTHREADS>>>(pred, grid, tbox, tcls, out);
}

// round 10
// speedup vs baseline: 1.1380x; 1.1380x over previous
#include <cuda_runtime.h>
#include <cuda_bf16.h>

// Yolov1 loss — persistent kernel, 2-stage cp.async ring, 28-cell tiles,
// 4 blocks/SM (592 blocks) to maximize warps/SM (latency hiding).
// B=16384, cells = 802816 = 28672 tiles of 28 cells.
// 592 * 8 = 4736 warp-streams; stream s handles tiles s, s+4736, ...
// Cell layout: [0:2) conf, [2:10) boxes (NB,4), [10:30) class logits.

#define NBLOCKS  592
#define NTHREADS 256
#define NSTREAMS (NBLOCKS * 8)   // 4736
#define NTILES   28672
#define TCELLS   28               // cells per tile
#define TWORDS   (TCELLS * 30)    // 840 words per tile
#define TF4      (TWORDS / 4)     // 210 float4 per tile

__device__ float g_partials[NBLOCKS];
__device__ unsigned int g_done = 0;   // atomicInc mod NBLOCKS -> self-resetting

__device__ __forceinline__ float fsig(float x) {
    float t;
    asm("tanh.approx.f32 %0, %1;" : "=f"(t) : "f"(x * 0.5f));
    return fmaf(t, 0.5f, 0.5f);
}
__device__ __forceinline__ float fsqrt_a(float x) {
    float r;
    asm("sqrt.approx.f32 %0, %1;" : "=f"(r) : "f"(x));
    return r;
}
__device__ __forceinline__ unsigned int smem_u32(const void* p) {
    return (unsigned int)__cvta_generic_to_shared(p);
}

// One cell's loss. p = 30 floats in smem; target data already in registers.
__device__ __forceinline__ float cell_loss(const float* __restrict__ p, int t,
                                           float4 tb, int g, int tc)
{
    const int s = t % 49;
    const float xg = (float)(s % 7);
    const float yg = (float)(s / 7);
    const float inv7 = 1.0f / 7.0f;
    const float tox = tb.x, toy = tb.y, tw = tb.z, th = tb.w;

    const float conf0 = fsig(p[0]);
    const float conf1 = fsig(p[1]);
    float pb[2][4];
    #pragma unroll
    for (int nb = 0; nb < 2; nb++)
        #pragma unroll
        for (int k = 0; k < 4; k++)
            pb[nb][k] = fsig(p[2 + nb * 4 + k]);

    float esum = 0.0f, et = 0.0f;
    #pragma unroll
    for (int j = 0; j < 20; j++) {
        const float e = __expf(p[10 + j]);
        esum += e;
        if (j == tc) et = e;
    }
    const float cls_t = __fdividef(et, esum);

    const float tcx = (xg + tox) * inv7;
    const float tcy = (yg + toy) * inv7;
    float iou[2];
    #pragma unroll
    for (int nb = 0; nb < 2; nb++) {
        const float pcx = (xg + pb[nb][0]) * inv7;
        const float pcy = (yg + pb[nb][1]) * inv7;
        const float pw = pb[nb][2], ph = pb[nb][3];
        const float tb_ = fminf(tcx + tw * 0.5f, pcx + pw * 0.5f)
                        - fmaxf(tcx - tw * 0.5f, pcx - pw * 0.5f);
        const float lr_ = fminf(tcy + th * 0.5f, pcy + ph * 0.5f)
                        - fmaxf(tcy - th * 0.5f, pcy - ph * 0.5f);
        const float inter = (tb_ < 0.0f || lr_ < 0.0f) ? 0.0f : tb_ * lr_;
        iou[nb] = __fdividef(inter, tw * th + pw * ph - inter);
    }

    const int best = (iou[1] > iou[0]) ? 1 : 0;
    const float iou_b  = iou[best];
    const float conf_b = best ? conf1 : conf0;

    const float d0 = pb[best][0] - tox;
    const float d1 = pb[best][1] - toy;
    const float d2 = fsqrt_a(pb[best][2]) - fsqrt_a(tw);
    const float d3 = fsqrt_a(pb[best][3]) - fsqrt_a(th);
    const float coord = d0 * d0 + d1 * d1 + d2 * d2 + d3 * d3;

    const float dc = conf_b - iou_b;
    const float dl = 1.0f - cls_t;
    const float obj_loss   = 5.0f * coord + dc * dc + dl * dl;
    const float noobj_loss = 0.5f * (conf0 * conf0 + conf1 * conf1);
    return (g == 1) ? obj_loss : noobj_loss;
}

// Issue one tile's cp.async copies (210 float4 spread over the warp), no commit.
__device__ __forceinline__ void issue_tile(float* __restrict__ dst,
                                           const float4* __restrict__ pred4,
                                           int tile, int lane)
{
    const float4* src = pred4 + (long)tile * TF4;
    #pragma unroll
    for (int i = 0; i < 7; i++) {
        const int idx = lane + i * 32;
        if (idx < TF4) {
            const unsigned int da = smem_u32(dst + idx * 4);
            asm volatile("cp.async.cg.shared.global [%0], [%1], 16;"
                         :: "r"(da), "l"(src + idx));
        }
    }
}

__global__ __launch_bounds__(NTHREADS, 4)
void yolo_loss_kernel(const float* __restrict__ pred,
                      const int*   __restrict__ grid,
                      const float* __restrict__ tbox,
                      const int*   __restrict__ tcls,
                      float* __restrict__ out)
{
    // 2 stages * 8 warps * 840 words = 13440 words = 53760 B
    __shared__ float sp[2 * 8 * TWORDS];

    const int lane = threadIdx.x & 31;
    const int wid  = threadIdx.x >> 5;
    const int stream = blockIdx.x * 8 + wid;
    const bool clane = (lane < TCELLS);   // compute lane

    float* const s0 = sp + wid * TWORDS;
    float* const s1 = sp + (8 + wid) * TWORDS;
    const float4* const tbox4 = reinterpret_cast<const float4*>(tbox);
    const float4* const pred4 = reinterpret_cast<const float4*>(pred);

    // ---- prologue: fill stage 0, prefetch tile-0 targets ----
    issue_tile(s0, pred4, stream, lane);
    asm volatile("cp.async.commit_group;");

    float4 tb = {}; int g = 0, tc = 0;
    if (clane) {
        const int c0 = stream * TCELLS + lane;
        tb = __ldg(tbox4 + c0);
        g  = __ldg(grid + c0);
        tc = __ldg(tcls + c0);
    }

    float v = 0.0f;
    int stage = 0;

    for (int it = 0; ; it++) {
        const int tn = stream + (it + 1) * NSTREAMS;
        const bool validn = (tn < NTILES);

        // issue next tile into the alternate stage; commit always (uniform count)
        if (validn) issue_tile(stage ? s0 : s1, pred4, tn, lane);
        asm volatile("cp.async.commit_group;");

        // register-prefetch next targets (overlaps current compute)
        float4 tbn = {}; int gn = 0, tcn = 0;
        if (validn && clane) {
            const int cn = tn * TCELLS + lane;
            tbn = __ldg(tbox4 + cn);
            gn  = __ldg(grid + cn);
            tcn = __ldg(tcls + cn);
        }

        if (validn) asm volatile("cp.async.wait_group 1;");
        else        asm volatile("cp.async.wait_group 0;");
        __syncwarp();

        if (clane) {
            const float* p = (stage ? s1 : s0) + lane * 30;
            const int t_cell = (stream + it * NSTREAMS) * TCELLS + lane;
            v += cell_loss(p, t_cell, tb, g, tc);
        }

        if (!validn) break;
        tb = tbn; g = gn; tc = tcn;
        stage ^= 1;
    }

    // ---- block reduction -> g_partials[blockIdx.x] ----
    #pragma unroll
    for (int o = 16; o; o >>= 1) v += __shfl_down_sync(0xffffffffu, v, o);
    __shared__ float wsum[NTHREADS / 32];
    __shared__ bool s_last;
    if (lane == 0) wsum[wid] = v;
    __syncthreads();
    if (threadIdx.x < NTHREADS / 32) {
        v = wsum[threadIdx.x];
        #pragma unroll
        for (int o = NTHREADS / 64; o; o >>= 1) v += __shfl_down_sync(0xffu, v, o);
        if (threadIdx.x == 0) {
            g_partials[blockIdx.x] = v;
            __threadfence();
            unsigned int prev = atomicInc(&g_done, NBLOCKS - 1);
            s_last = (prev == NBLOCKS - 1);
        }
    }
    __syncthreads();

    // ---- last-arriving block: deterministic final reduction ----
    if (s_last) {
        double acc = 0.0;
        for (int i = threadIdx.x; i < NBLOCKS; i += NTHREADS)
            acc += (double)g_partials[i];
        #pragma unroll
        for (int o = 16; o; o >>= 1) acc += __shfl_down_sync(0xffffffffu, acc, o);
        __shared__ double ws[NTHREADS / 32];
        if (lane == 0) ws[wid] = acc;
        __syncthreads();
        if (threadIdx.x == 0) {
            double sum = 0.0;
            #pragma unroll
            for (int i = 0; i < NTHREADS / 32; i++) sum += ws[i];
            out[0] = (float)(sum / 16384.0);
        }
    }
}

extern "C" void kernel_launch(void* const* d_in, const int* in_sizes, int n_in,
                              void* d_out, int out_size)
{
    const float* pred = (const float*)d_in[0];   // (B, 1470) f32
    const int*   grid = (const int*)  d_in[1];   // (B, 7, 7) i32
    const float* tbox = (const float*)d_in[2];   // (B, 7, 7, 4) f32
    const int*   tcls = (const int*)  d_in[3];   // (B, 7, 7) i32
    float* out = (float*)d_out;

    yolo_loss_kernel<<<NBLOCKS, NTHREADS>>>(pred, grid, tbox, tcls, out);
}

// round 11
// speedup vs baseline: 1.2309x; 1.0816x over previous
#include <cuda_runtime.h>
#include <cuda_bf16.h>

// Yolov1 loss — persistent kernel, 2-stage cp.async ring, 32-cell tiles,
// contiguous per-warp tile runs with remainder spread across blocks.
// B=16384, cells = 802816 = 25088 tiles of 32 cells.
// 444 blocks * 8 warps = 3552 streams. sid = wid*444 + blockIdx.x (transposed so
// the 224 long streams land on warp 0 of 224 DIFFERENT blocks).
// stream sid: start = sid*7 + min(sid,224), cnt = 7 + (sid<224).
// Cell layout: [0:2) conf, [2:10) boxes (NB,4), [10:30) class logits.

#define NBLOCKS  444
#define NTHREADS 256
#define NSTREAMS (NBLOCKS * 8)   // 3552
#define NTILES   25088
#define NEXTRA   (NTILES - NSTREAMS * 7)   // 224

__device__ float g_partials[NBLOCKS];
__device__ unsigned int g_done = 0;   // atomicInc mod NBLOCKS -> self-resetting

__device__ __forceinline__ float fsig(float x) {
    float t;
    asm("tanh.approx.f32 %0, %1;" : "=f"(t) : "f"(x * 0.5f));
    return fmaf(t, 0.5f, 0.5f);
}
__device__ __forceinline__ float fsqrt_a(float x) {
    float r;
    asm("sqrt.approx.f32 %0, %1;" : "=f"(r) : "f"(x));
    return r;
}
__device__ __forceinline__ unsigned int smem_u32(const void* p) {
    return (unsigned int)__cvta_generic_to_shared(p);
}

// One cell's loss. p = 30 floats in smem; target data already in registers.
__device__ __forceinline__ float cell_loss(const float* __restrict__ p, int t,
                                           float4 tb, int g, int tc)
{
    const int s = t % 49;
    const float xg = (float)(s % 7);
    const float yg = (float)(s / 7);
    const float inv7 = 1.0f / 7.0f;
    const float tox = tb.x, toy = tb.y, tw = tb.z, th = tb.w;

    const float conf0 = fsig(p[0]);
    const float conf1 = fsig(p[1]);
    float pb[2][4];
    #pragma unroll
    for (int nb = 0; nb < 2; nb++)
        #pragma unroll
        for (int k = 0; k < 4; k++)
            pb[nb][k] = fsig(p[2 + nb * 4 + k]);

    float esum = 0.0f, et = 0.0f;
    #pragma unroll
    for (int j = 0; j < 20; j++) {
        const float e = __expf(p[10 + j]);
        esum += e;
        if (j == tc) et = e;
    }
    const float cls_t = __fdividef(et, esum);

    const float tcx = (xg + tox) * inv7;
    const float tcy = (yg + toy) * inv7;
    float iou[2];
    #pragma unroll
    for (int nb = 0; nb < 2; nb++) {
        const float pcx = (xg + pb[nb][0]) * inv7;
        const float pcy = (yg + pb[nb][1]) * inv7;
        const float pw = pb[nb][2], ph = pb[nb][3];
        const float tb_ = fminf(tcx + tw * 0.5f, pcx + pw * 0.5f)
                        - fmaxf(tcx - tw * 0.5f, pcx - pw * 0.5f);
        const float lr_ = fminf(tcy + th * 0.5f, pcy + ph * 0.5f)
                        - fmaxf(tcy - th * 0.5f, pcy - ph * 0.5f);
        const float inter = (tb_ < 0.0f || lr_ < 0.0f) ? 0.0f : tb_ * lr_;
        iou[nb] = __fdividef(inter, tw * th + pw * ph - inter);
    }

    const int best = (iou[1] > iou[0]) ? 1 : 0;
    const float iou_b  = iou[best];
    const float conf_b = best ? conf1 : conf0;

    const float d0 = pb[best][0] - tox;
    const float d1 = pb[best][1] - toy;
    const float d2 = fsqrt_a(pb[best][2]) - fsqrt_a(tw);
    const float d3 = fsqrt_a(pb[best][3]) - fsqrt_a(th);
    const float coord = d0 * d0 + d1 * d1 + d2 * d2 + d3 * d3;

    const float dc = conf_b - iou_b;
    const float dl = 1.0f - cls_t;
    const float obj_loss   = 5.0f * coord + dc * dc + dl * dl;
    const float noobj_loss = 0.5f * (conf0 * conf0 + conf1 * conf1);
    return (g == 1) ? obj_loss : noobj_loss;
}

// Issue one tile's cp.async copies (240 float4 spread over the warp), no commit.
__device__ __forceinline__ void issue_tile(float* __restrict__ dst,
                                           const float4* __restrict__ pred4,
                                           int tile, int lane)
{
    const float4* src = pred4 + (long)tile * 240;
    #pragma unroll
    for (int i = 0; i < 8; i++) {
        const int idx = lane + i * 32;
        if (idx < 240) {
            const unsigned int da = smem_u32(dst + idx * 4);
            asm volatile("cp.async.cg.shared.global [%0], [%1], 16;"
                         :: "r"(da), "l"(src + idx));
        }
    }
}

__global__ __launch_bounds__(NTHREADS, 3)
void yolo_loss_kernel(const float* __restrict__ pred,
                      const int*   __restrict__ grid,
                      const float* __restrict__ tbox,
                      const int*   __restrict__ tcls,
                      float* __restrict__ out)
{
    // 2 stages * 8 warps * (32 cells * 30 words) = 61440 B
    __shared__ float sp[2 * 8 * 960];

    const int lane = threadIdx.x & 31;
    const int wid  = threadIdx.x >> 5;

    // Transposed stream id: extras (sid < 224) fall on warp 0 of blocks 0..223.
    const int sid   = wid * NBLOCKS + blockIdx.x;
    const int start = sid * 7 + min(sid, NEXTRA);
    const int cnt   = 7 + (sid < NEXTRA ? 1 : 0);

    float* const s0 = sp + wid * 960;
    float* const s1 = sp + (8 + wid) * 960;
    const float4* const tbox4 = reinterpret_cast<const float4*>(tbox);
    const float4* const pred4 = reinterpret_cast<const float4*>(pred);

    // ---- prologue: fill stage 0, prefetch tile-0 targets ----
    issue_tile(s0, pred4, start, lane);
    asm volatile("cp.async.commit_group;");

    {
        const int c0 = start * 32 + lane;
        float4 tb = __ldg(tbox4 + c0);
        int    g  = __ldg(grid + c0);
        int    tc = __ldg(tcls + c0);

        float v = 0.0f;
        int stage = 0;

        for (int it = 0; ; it++) {
            const bool validn = (it + 1 < cnt);
            const int tn = start + it + 1;

            // issue next tile into the alternate stage; commit always (uniform count)
            if (validn) issue_tile(stage ? s0 : s1, pred4, tn, lane);
            asm volatile("cp.async.commit_group;");

            // register-prefetch next targets (overlaps current compute)
            float4 tbn = {}; int gn = 0, tcn = 0;
            if (validn) {
                const int cn = tn * 32 + lane;
                tbn = __ldg(tbox4 + cn);
                gn  = __ldg(grid + cn);
                tcn = __ldg(tcls + cn);
            }

            if (validn) asm volatile("cp.async.wait_group 1;");
            else        asm volatile("cp.async.wait_group 0;");
            __syncwarp();

            const float* p = (stage ? s1 : s0) + lane * 30;
            const int t_cell = (start + it) * 32 + lane;
            v += cell_loss(p, t_cell, tb, g, tc);

            if (!validn) break;
            tb = tbn; g = gn; tc = tcn;
            stage ^= 1;
        }

        // ---- block reduction -> g_partials[blockIdx.x] ----
        #pragma unroll
        for (int o = 16; o; o >>= 1) v += __shfl_down_sync(0xffffffffu, v, o);
        __shared__ float wsum[NTHREADS / 32];
        __shared__ bool s_last;
        if (lane == 0) wsum[wid] = v;
        __syncthreads();
        if (threadIdx.x < NTHREADS / 32) {
            v = wsum[threadIdx.x];
            #pragma unroll
            for (int o = NTHREADS / 64; o; o >>= 1) v += __shfl_down_sync(0xffu, v, o);
            if (threadIdx.x == 0) {
                g_partials[blockIdx.x] = v;
                __threadfence();
                unsigned int prev = atomicInc(&g_done, NBLOCKS - 1);
                s_last = (prev == NBLOCKS - 1);
            }
        }
        __syncthreads();

        // ---- last-arriving block: deterministic final reduction ----
        if (s_last) {
            double acc = 0.0;
            for (int i = threadIdx.x; i < NBLOCKS; i += NTHREADS)
                acc += (double)g_partials[i];
            #pragma unroll
            for (int o = 16; o; o >>= 1) acc += __shfl_down_sync(0xffffffffu, acc, o);
            __shared__ double ws[NTHREADS / 32];
            if (lane == 0) ws[wid] = acc;
            __syncthreads();
            if (threadIdx.x == 0) {
                double sum = 0.0;
                #pragma unroll
                for (int i = 0; i < NTHREADS / 32; i++) sum += ws[i];
                out[0] = (float)(sum / 16384.0);
            }
        }
    }
}

extern "C" void kernel_launch(void* const* d_in, const int* in_sizes, int n_in,
                              void* d_out, int out_size)
{
    const float* pred = (const float*)d_in[0];   // (B, 1470) f32
    const int*   grid = (const int*)  d_in[1];   // (B, 7, 7) i32
    const float* tbox = (const float*)d_in[2];   // (B, 7, 7, 4) f32
    const int*   tcls = (const int*)  d_in[3];   // (B, 7, 7) i32
    float* out = (float*)d_out;

    yolo_loss_kernel<<<NBLOCKS, NTHREADS>>>(pred, grid, tbox, tcls, out);
}